// round 1
// baseline (speedup 1.0000x reference)
#include <cuda_runtime.h>
#include <math.h>

#define BATCH 8
#define C 128
#define NN 4096          // H*W = 64*64
#define D 16             // q/k head dim
#define G 32             // groups
#define CPG (C / G)      // 4 channels per group
#define QM 128           // query tile
#define KT 32            // key tile
#define EPS 1e-5f

// ---------------- scratch (static device allocations are the allowed path) ----
__device__ float g_h[BATCH * C * NN];   // group-normed activations [B,C,N]
__device__ float g_q[BATCH * D * NN];   // q [B,D,N]
__device__ float g_k[BATCH * D * NN];   // k [B,D,N]
__device__ float g_v[BATCH * C * NN];   // v [B,C,N]
__device__ float g_a[BATCH * C * NN];   // attn output [B,C,N]

// ---------------- GroupNorm -------------------------------------------------
__global__ __launch_bounds__(256) void gn_kernel(
    const float* __restrict__ x, const float* __restrict__ w,
    const float* __restrict__ bvec, float* __restrict__ h)
{
    const int b = blockIdx.x >> 5;
    const int g = blockIdx.x & 31;
    const int c0 = g * CPG;
    const float* xp = x + ((size_t)b * C + c0) * NN;
    float* hp = h + ((size_t)b * C + c0) * NN;

    const int TOT = CPG * NN;   // 16384
    float s = 0.f, s2 = 0.f;
    for (int idx = threadIdx.x; idx < TOT; idx += 256) {
        float v = xp[idx];
        s += v; s2 += v * v;
    }
    // block reduce (warp shuffle + smem)
    __shared__ float red[16];
    int lane = threadIdx.x & 31, wid = threadIdx.x >> 5;
    #pragma unroll
    for (int o = 16; o > 0; o >>= 1) {
        s  += __shfl_xor_sync(0xffffffffu, s,  o);
        s2 += __shfl_xor_sync(0xffffffffu, s2, o);
    }
    if (lane == 0) { red[wid] = s; red[8 + wid] = s2; }
    __syncthreads();
    if (wid == 0) {
        float a = (lane < 8) ? red[lane] : 0.f;
        float a2 = (lane < 8) ? red[8 + lane] : 0.f;
        #pragma unroll
        for (int o = 4; o > 0; o >>= 1) {
            a  += __shfl_xor_sync(0xffffffffu, a,  o);
            a2 += __shfl_xor_sync(0xffffffffu, a2, o);
        }
        if (lane == 0) { red[0] = a; red[1] = a2; }
    }
    __syncthreads();
    const float inv_n = 1.f / (float)TOT;
    float mean = red[0] * inv_n;
    float var = red[1] * inv_n - mean * mean;
    float inv = rsqrtf(var + EPS);

    for (int idx = threadIdx.x; idx < TOT; idx += 256) {
        int c = idx >> 12;   // idx / NN
        float v = (xp[idx] - mean) * inv;
        hp[idx] = v * w[c0 + c] + bvec[c0 + c];
    }
}

// ---------------- channel matmul: out[b,e,n] = sum_c W[e,c]*in[b,c,n] + bias[e]
// optional residual add (for final projection).
template <int E, int EPT, bool ADDX>
__global__ __launch_bounds__(256) void chanmm_kernel(
    const float* __restrict__ W, const float* __restrict__ bias,
    const float* __restrict__ in, const float* __restrict__ xres,
    float* __restrict__ out)
{
    __shared__ float w_s[EPT][C];
    const int e0 = blockIdx.y * EPT;
    const int b = blockIdx.z;

    for (int idx = threadIdx.x; idx < EPT * C; idx += 256)
        w_s[idx >> 7][idx & 127] = W[(e0 + (idx >> 7)) * C + (idx & 127)];
    __syncthreads();

    const int n = blockIdx.x * 256 + threadIdx.x;
    float acc[EPT];
    #pragma unroll
    for (int e = 0; e < EPT; e++) acc[e] = bias[e0 + e];

    const float* ip = in + (size_t)b * C * NN + n;
    #pragma unroll 8
    for (int c = 0; c < C; c++) {
        float hv = __ldg(ip + (size_t)c * NN);
        #pragma unroll
        for (int e = 0; e < EPT; e++) acc[e] += w_s[e][c] * hv;
    }
    #pragma unroll
    for (int e = 0; e < EPT; e++) {
        float r = acc[e];
        if (ADDX) r += xres[((size_t)b * C + e0 + e) * NN + n];
        out[((size_t)b * E + e0 + e) * NN + n] = r;
    }
}

// ---------------- flash attention -------------------------------------------
// Per block: batch b, 128-query tile. Online softmax over 4096 keys in tiles
// of 32. Accumulator: each thread owns 8 query rows x 8 v-channels.
__global__ __launch_bounds__(256) void flash_kernel(
    const float* __restrict__ gq, const float* __restrict__ gk,
    const float* __restrict__ gv, float* __restrict__ ga)
{
    const int b = blockIdx.x >> 5;        // 32 query tiles per batch
    const int q0 = (blockIdx.x & 31) * QM;
    const int t = threadIdx.x;

    __shared__ float q_s[QM][D + 1];      // padded: conflict-free row reads
    __shared__ float k_s[D][KT];          // [d][j]
    __shared__ float v_s[KT][C + 4];      // padded for STS/LDS conflicts
    __shared__ float p_s[QM][KT];
    __shared__ float m_s[QM], l_s[QM], al_s[QM];

    // load Q tile, pre-scaled by 1/sqrt(D) = 0.25
    for (int idx = t; idx < QM * D; idx += 256) {
        int d = idx >> 7, i = idx & 127;            // idx = d*QM + i (coalesced i)
        q_s[i][d] = gq[((size_t)b * D + d) * NN + q0 + i] * 0.25f;
    }
    if (t < QM) { m_s[t] = -1e30f; l_s[t] = 0.f; }

    float o[8][8];
    #pragma unroll
    for (int r = 0; r < 8; r++)
        #pragma unroll
        for (int cc = 0; cc < 8; cc++) o[r][cc] = 0.f;

    const int ty = t >> 4, tx = t & 15;
    const int i0 = ty * 8, c0 = tx * 8;
    const int irow = t >> 1, half = t & 1;    // score phase: 2 threads per row

    __syncthreads();

    for (int j0 = 0; j0 < NN; j0 += KT) {
        // K tile: k_s[d][j]  (consecutive j -> coalesced gmem, conflict-free STS)
        for (int idx = t; idx < D * KT; idx += 256) {
            int d = idx >> 5, j = idx & 31;
            k_s[d][j] = gk[((size_t)b * D + d) * NN + j0 + j];
        }
        // V tile: v_s[j][c]  from gv[b,c,j] (coalesced j)
        for (int idx = t; idx < C * KT; idx += 256) {
            int c = idx >> 5, j = idx & 31;
            v_s[j][c] = gv[((size_t)b * C + c) * NN + j0 + j];
        }
        __syncthreads();

        // ---- scores for row irow, columns half*16 .. half*16+15
        float s[16];
        #pragma unroll
        for (int jj = 0; jj < 16; jj++) s[jj] = 0.f;
        #pragma unroll
        for (int d = 0; d < D; d++) {
            float qd = q_s[irow][d];
            #pragma unroll
            for (int jj = 0; jj < 16; jj++) s[jj] += qd * k_s[d][half * 16 + jj];
        }
        float mx = s[0];
        #pragma unroll
        for (int jj = 1; jj < 16; jj++) mx = fmaxf(mx, s[jj]);
        mx = fmaxf(mx, __shfl_xor_sync(0xffffffffu, mx, 1));
        float m_old = m_s[irow];
        float m_new = fmaxf(m_old, mx);
        float sum = 0.f;
        #pragma unroll
        for (int jj = 0; jj < 16; jj++) {
            float p = __expf(s[jj] - m_new);
            p_s[irow][half * 16 + jj] = p;
            sum += p;
        }
        sum += __shfl_xor_sync(0xffffffffu, sum, 1);
        if (half == 0) {
            float al = __expf(m_old - m_new);   // 0 on first tile (m_old=-1e30)
            al_s[irow] = al;
            l_s[irow] = l_s[irow] * al + sum;
            m_s[irow] = m_new;
        }
        __syncthreads();

        // ---- rescale + P*V accumulate
        #pragma unroll
        for (int r = 0; r < 8; r++) {
            float al = al_s[i0 + r];
            #pragma unroll
            for (int cc = 0; cc < 8; cc++) o[r][cc] *= al;
        }
        #pragma unroll 4
        for (int j = 0; j < KT; j++) {
            float4 va = *(const float4*)&v_s[j][c0];
            float4 vb = *(const float4*)&v_s[j][c0 + 4];
            #pragma unroll
            for (int r = 0; r < 8; r++) {
                float p = p_s[i0 + r][j];
                o[r][0] += p * va.x; o[r][1] += p * va.y;
                o[r][2] += p * va.z; o[r][3] += p * va.w;
                o[r][4] += p * vb.x; o[r][5] += p * vb.y;
                o[r][6] += p * vb.z; o[r][7] += p * vb.w;
            }
        }
        __syncthreads();
    }

    // epilogue: normalize and write a[b,c,n]
    #pragma unroll
    for (int r = 0; r < 8; r++) {
        float invl = 1.f / l_s[i0 + r];
        #pragma unroll
        for (int cc = 0; cc < 8; cc++) {
            ga[((size_t)b * C + c0 + cc) * NN + q0 + i0 + r] = o[r][cc] * invl;
        }
    }
}

// ---------------- launch -----------------------------------------------------
extern "C" void kernel_launch(void* const* d_in, const int* in_sizes, int n_in,
                              void* d_out, int out_size)
{
    const float* x    = (const float*)d_in[0];
    const float* gn_w = (const float*)d_in[1];
    const float* gn_b = (const float*)d_in[2];
    const float* q_w  = (const float*)d_in[3];
    const float* q_b  = (const float*)d_in[4];
    const float* k_w  = (const float*)d_in[5];
    const float* k_b  = (const float*)d_in[6];
    const float* v_w  = (const float*)d_in[7];
    const float* v_b  = (const float*)d_in[8];
    const float* p_w  = (const float*)d_in[9];
    const float* p_b  = (const float*)d_in[10];
    float* out = (float*)d_out;

    float *h, *q, *k, *v, *a;
    cudaGetSymbolAddress((void**)&h, g_h);
    cudaGetSymbolAddress((void**)&q, g_q);
    cudaGetSymbolAddress((void**)&k, g_k);
    cudaGetSymbolAddress((void**)&v, g_v);
    cudaGetSymbolAddress((void**)&a, g_a);

    // 1. GroupNorm
    gn_kernel<<<BATCH * G, 256>>>(x, gn_w, gn_b, h);

    // 2. q, k, v projections (1x1 convs)
    chanmm_kernel<D, 8, false><<<dim3(NN / 256, D / 8, BATCH), 256>>>(q_w, q_b, h, nullptr, q);
    chanmm_kernel<D, 8, false><<<dim3(NN / 256, D / 8, BATCH), 256>>>(k_w, k_b, h, nullptr, k);
    chanmm_kernel<C, 8, false><<<dim3(NN / 256, C / 8, BATCH), 256>>>(v_w, v_b, h, nullptr, v);

    // 3. attention (flash, online softmax)
    flash_kernel<<<BATCH * (NN / QM), 256>>>(q, k, v, a);

    // 4. output projection + residual
    chanmm_kernel<C, 8, true><<<dim3(NN / 256, C / 8, BATCH), 256>>>(p_w, p_b, a, x, out);
}